// round 6
// baseline (speedup 1.0000x reference)
#include <cuda_runtime.h>
#include <cuda_bf16.h>
#include <cuda_fp16.h>
#include <cstdint>

#define NN 10000
#define NE 320000
#define F_HID 256

// ---------------- scratch (device globals; no allocation allowed) ----------------
__device__ int   g_deg[NN];
__device__ int   g_incnt[NN];
__device__ int   g_roff[NN + 1];
__device__ int   g_rank[NE];
__device__ float g_inv[NN];
__device__ int2  g_csr[NE];                         // (src, w bits) interleaved
__device__ float g_buf[NN * F_HID];                 // fp32 layer-3 output
__device__ __align__(16) __half g_x16[NN * F_HID];  // fp16 gather operand
__device__ __nv_bfloat16 g_ahi[NN * F_HID];         // bf16 hi of GEMM input
__device__ __nv_bfloat16 g_alo[NN * F_HID];         // bf16 lo
__device__ __nv_bfloat16 g_whi[256 * 256 * 3];      // converted weights
__device__ __nv_bfloat16 g_wlo[256 * 256 * 3];
__device__ float g_vsum;

// ---------------- helpers ----------------
__device__ __forceinline__ void cvt_hilo2(float x0, float x1, uint32_t& hip, uint32_t& lop) {
    __nv_bfloat162 h = __floats2bfloat162_rn(x0, x1);
    float h0 = __bfloat162float(__low2bfloat16(h));
    float h1 = __bfloat162float(__high2bfloat16(h));
    __nv_bfloat162 l = __floats2bfloat162_rn(x0 - h0, x1 - h1);
    hip = *reinterpret_cast<uint32_t*>(&h);
    lop = *reinterpret_cast<uint32_t*>(&l);
}

__device__ __forceinline__ void ldsm4(uint32_t* r, uint32_t addr) {
    asm volatile("ldmatrix.sync.aligned.m8n8.x4.shared.b16 {%0,%1,%2,%3}, [%4];"
                 : "=r"(r[0]), "=r"(r[1]), "=r"(r[2]), "=r"(r[3]) : "r"(addr));
}
__device__ __forceinline__ void ldsm4t(uint32_t* r, uint32_t addr) {
    asm volatile("ldmatrix.sync.aligned.m8n8.x4.trans.shared.b16 {%0,%1,%2,%3}, [%4];"
                 : "=r"(r[0]), "=r"(r[1]), "=r"(r[2]), "=r"(r[3]) : "r"(addr));
}
__device__ __forceinline__ void mma16816(float* c, const uint32_t* a, const uint32_t* b) {
    asm volatile(
        "mma.sync.aligned.m16n8k16.row.col.f32.bf16.bf16.f32 "
        "{%0,%1,%2,%3}, {%4,%5,%6,%7}, {%8,%9}, {%0,%1,%2,%3};"
        : "+f"(c[0]), "+f"(c[1]), "+f"(c[2]), "+f"(c[3])
        : "r"(a[0]), "r"(a[1]), "r"(a[2]), "r"(a[3]), "r"(b[0]), "r"(b[1]));
}

// ---------------- graph preprocessing ----------------
__global__ void zero_kernel() {
    int i = blockIdx.x * blockDim.x + threadIdx.x;
    if (i < NN) { g_deg[i] = 0; g_incnt[i] = 0; }
    if (i == 0) g_vsum = 0.0f;
}

__global__ void count_kernel(const int* __restrict__ src, const int* __restrict__ dst) {
    int e = blockIdx.x * blockDim.x + threadIdx.x;
    if (e < NE) {
        atomicAdd(&g_deg[src[e]], 1);
        g_rank[e] = atomicAdd(&g_incnt[dst[e]], 1);
    }
}

__global__ void scan_kernel() {
    __shared__ int carry;
    __shared__ int wsum[32];
    int tid = threadIdx.x;  // 1024 threads
    if (tid == 0) carry = 0;
    __syncthreads();
    for (int base = 0; base < NN; base += 1024) {
        int i = base + tid;
        int v = (i < NN) ? g_incnt[i] : 0;
        int x = v;
        #pragma unroll
        for (int o = 1; o < 32; o <<= 1) {
            int y = __shfl_up_sync(0xffffffffu, x, o);
            if ((tid & 31) >= o) x += y;
        }
        if ((tid & 31) == 31) wsum[tid >> 5] = x;
        __syncthreads();
        if (tid < 32) {
            int s = wsum[tid];
            int t = s;
            #pragma unroll
            for (int o = 1; o < 32; o <<= 1) {
                int y = __shfl_up_sync(0xffffffffu, t, o);
                if (tid >= o) t += y;
            }
            wsum[tid] = t - s;
        }
        __syncthreads();
        int incl = x + wsum[tid >> 5] + carry;
        if (i < NN) g_roff[i + 1] = incl;
        __syncthreads();
        if (tid == 1023) carry = incl;
        __syncthreads();
    }
    if (tid == 0) g_roff[0] = 0;
    for (int i = tid; i < NN; i += 1024) {
        int d = g_deg[i];
        g_inv[i] = (d > 0) ? 1.0f / (float)d : 0.0f;
    }
}

__global__ void fill_kernel(const int* __restrict__ src, const int* __restrict__ dst) {
    int e = blockIdx.x * blockDim.x + threadIdx.x;
    if (e < NE) {
        int d = dst[e];
        int s = src[e];
        int p = g_roff[d] + g_rank[e];
        g_csr[p] = make_int2(s, __float_as_int(g_inv[s]));
    }
}

// ---------------- conversions ----------------
__global__ void convert_w(const float* __restrict__ W, int n, int off) {
    int i = 2 * (blockIdx.x * blockDim.x + threadIdx.x);
    if (i < n) {
        float2 v = *(const float2*)(W + i);
        uint32_t hip, lop;
        cvt_hilo2(v.x, v.y, hip, lop);
        *(uint32_t*)((char*)g_whi + 2 * (off + i)) = hip;
        *(uint32_t*)((char*)g_wlo + 2 * (off + i)) = lop;
    }
}

__global__ void convert_x16(const float* __restrict__ X, int n) {
    int i = 2 * (blockIdx.x * blockDim.x + threadIdx.x);
    if (i < n) {
        float2 v = *(const float2*)(X + i);
        __half2 h = __floats2half2_rn(v.x, v.y);
        *(uint32_t*)((char*)g_x16 + 2 * i) = *reinterpret_cast<uint32_t*>(&h);
    }
}

// ---------------- edge aggregation (fp16 gather, fp32 accum) -> bf16 hi/lo ----------------
// Gather and write use the SAME element mapping: CHUNKS=1 -> lane*4+{0..3};
// CHUNKS=2 -> lane*8+{0..7} (acc0 = +0..3, acc1 = +4..7), written as one uint4.
template <int CHUNKS>  // 1: F=128, 2: F=256
__global__ void aggregate_kernel(const __half* __restrict__ X,
                                 __nv_bfloat16* __restrict__ Yhi,
                                 __nv_bfloat16* __restrict__ Ylo, int F) {
    int gw    = (blockIdx.x * blockDim.x + threadIdx.x) >> 5;
    int lane  = threadIdx.x & 31;
    int nwrp  = (gridDim.x * blockDim.x) >> 5;
    for (int n = gw; n < NN; n += nwrp) {
        int s0 = g_roff[n], s1 = g_roff[n + 1];
        float4 acc0 = make_float4(0.f, 0.f, 0.f, 0.f);
        float4 acc1 = make_float4(0.f, 0.f, 0.f, 0.f);
        for (int e0 = s0; e0 < s1; e0 += 32) {
            int e = e0 + lane;
            int   ss = 0; float ww = 0.f;
            if (e < s1) {
                int2 ev = g_csr[e];
                ss = ev.x; ww = __int_as_float(ev.y);
            }
            int cnt = min(32, s1 - e0);
            for (int j = 0; j < cnt; j++) {
                int   sj = __shfl_sync(0xffffffffu, ss, j);
                float wj = __shfl_sync(0xffffffffu, ww, j);
                const __half* xp = X + (size_t)sj * F;
                if (CHUNKS == 1) {
                    uint2 v = ((const uint2*)xp)[lane];
                    float2 f0 = __half22float2(*reinterpret_cast<__half2*>(&v.x));
                    float2 f1 = __half22float2(*reinterpret_cast<__half2*>(&v.y));
                    acc0.x += wj * f0.x; acc0.y += wj * f0.y;
                    acc0.z += wj * f1.x; acc0.w += wj * f1.y;
                } else {
                    uint4 v = ((const uint4*)xp)[lane];
                    float2 f0 = __half22float2(*reinterpret_cast<__half2*>(&v.x));
                    float2 f1 = __half22float2(*reinterpret_cast<__half2*>(&v.y));
                    float2 f2 = __half22float2(*reinterpret_cast<__half2*>(&v.z));
                    float2 f3 = __half22float2(*reinterpret_cast<__half2*>(&v.w));
                    acc0.x += wj * f0.x; acc0.y += wj * f0.y;
                    acc0.z += wj * f1.x; acc0.w += wj * f1.y;
                    acc1.x += wj * f2.x; acc1.y += wj * f2.y;
                    acc1.z += wj * f3.x; acc1.w += wj * f3.y;
                }
            }
        }
        uint32_t h01, l01, h23, l23;
        cvt_hilo2(acc0.x, acc0.y, h01, l01);
        cvt_hilo2(acc0.z, acc0.w, h23, l23);
        if (CHUNKS == 1) {
            ((uint2*)(Yhi + (size_t)n * F))[lane] = make_uint2(h01, h23);
            ((uint2*)(Ylo + (size_t)n * F))[lane] = make_uint2(l01, l23);
        } else {
            uint32_t h45, l45, h67, l67;
            cvt_hilo2(acc1.x, acc1.y, h45, l45);
            cvt_hilo2(acc1.z, acc1.w, h67, l67);
            ((uint4*)(Yhi + (size_t)n * F))[lane] = make_uint4(h01, h23, h45, h67);
            ((uint4*)(Ylo + (size_t)n * F))[lane] = make_uint4(l01, l23, l45, l67);
        }
    }
}

// ---------------- GEMM via mma.sync bf16 hi/lo ----------------
// CTA tile 128x128, 8 warps (2m x 4n), warp tile 64x32, BK=32
// mode 0: relu + fp16 out (C16);  mode 1: no act + fp32 out (C32)
#define AS_STRIDE 40
#define BS_STRIDE 136
__global__ void __launch_bounds__(256)
gemm_mma(const __nv_bfloat16* __restrict__ Ahi, const __nv_bfloat16* __restrict__ Alo,
         const __nv_bfloat16* __restrict__ Whi, const __nv_bfloat16* __restrict__ Wlo,
         const float* __restrict__ bias, float* __restrict__ C32,
         __half* __restrict__ C16, int K, int mode) {
    __shared__ __align__(16) __nv_bfloat16 sAhi[128 * AS_STRIDE];
    __shared__ __align__(16) __nv_bfloat16 sAlo[128 * AS_STRIDE];
    __shared__ __align__(16) __nv_bfloat16 sBhi[32 * BS_STRIDE];
    __shared__ __align__(16) __nv_bfloat16 sBlo[32 * BS_STRIDE];
    __shared__ float sbias[128];

    int tid = threadIdx.x;
    int m0 = blockIdx.x * 128, n0 = blockIdx.y * 128;
    if (tid < 128) sbias[tid] = bias[n0 + tid];
    int wid = tid >> 5, lane = tid & 31;
    int wm = (wid & 1) * 64, wn = (wid >> 1) * 32;

    float acc[4][4][4];
    #pragma unroll
    for (int i = 0; i < 4; i++)
        #pragma unroll
        for (int j = 0; j < 4; j++)
            #pragma unroll
            for (int q = 0; q < 4; q++) acc[i][j][q] = 0.f;

    const uint4 z4 = make_uint4(0, 0, 0, 0);

    for (int kc = 0; kc < K; kc += 32) {
        #pragma unroll
        for (int idx = tid; idx < 512; idx += 256) {
            int row = idx >> 2, c16 = idx & 3;
            int gr = m0 + row;
            uint4 vh = z4, vl = z4;
            if (gr < NN) {
                vh = *(const uint4*)(Ahi + (size_t)gr * K + kc + c16 * 8);
                vl = *(const uint4*)(Alo + (size_t)gr * K + kc + c16 * 8);
            }
            *(uint4*)(sAhi + row * AS_STRIDE + c16 * 8) = vh;
            *(uint4*)(sAlo + row * AS_STRIDE + c16 * 8) = vl;
        }
        #pragma unroll
        for (int idx = tid; idx < 512; idx += 256) {
            int row = idx >> 4, c16 = idx & 15;
            *(uint4*)(sBhi + row * BS_STRIDE + c16 * 8) =
                *(const uint4*)(Whi + (size_t)(kc + row) * 256 + n0 + c16 * 8);
            *(uint4*)(sBlo + row * BS_STRIDE + c16 * 8) =
                *(const uint4*)(Wlo + (size_t)(kc + row) * 256 + n0 + c16 * 8);
        }
        __syncthreads();

        #pragma unroll
        for (int k16 = 0; k16 < 2; k16++) {
            uint32_t ah[4][4], al[4][4], bh[4][2], bl[4][2];
            #pragma unroll
            for (int mt = 0; mt < 4; mt++) {
                int row = wm + mt * 16 + (lane & 15);
                int col = k16 * 16 + (lane >> 4) * 8;
                uint32_t ad = (uint32_t)__cvta_generic_to_shared(sAhi + row * AS_STRIDE + col);
                ldsm4(ah[mt], ad);
                ad = (uint32_t)__cvta_generic_to_shared(sAlo + row * AS_STRIDE + col);
                ldsm4(al[mt], ad);
            }
            #pragma unroll
            for (int nt2 = 0; nt2 < 2; nt2++) {
                int row = k16 * 16 + (lane & 15);
                int col = wn + nt2 * 16 + ((lane >> 4) & 1) * 8;
                uint32_t t[4];
                uint32_t ad = (uint32_t)__cvta_generic_to_shared(sBhi + row * BS_STRIDE + col);
                ldsm4t(t, ad);
                bh[nt2 * 2][0] = t[0]; bh[nt2 * 2][1] = t[1];
                bh[nt2 * 2 + 1][0] = t[2]; bh[nt2 * 2 + 1][1] = t[3];
                ad = (uint32_t)__cvta_generic_to_shared(sBlo + row * BS_STRIDE + col);
                ldsm4t(t, ad);
                bl[nt2 * 2][0] = t[0]; bl[nt2 * 2][1] = t[1];
                bl[nt2 * 2 + 1][0] = t[2]; bl[nt2 * 2 + 1][1] = t[3];
            }
            #pragma unroll
            for (int mt = 0; mt < 4; mt++)
                #pragma unroll
                for (int nt = 0; nt < 4; nt++) {
                    mma16816(acc[mt][nt], ah[mt], bh[nt]);
                    mma16816(acc[mt][nt], ah[mt], bl[nt]);
                    mma16816(acc[mt][nt], al[mt], bh[nt]);
                }
        }
        __syncthreads();
    }

    // epilogue
    #pragma unroll
    for (int mt = 0; mt < 4; mt++) {
        int r0 = m0 + wm + mt * 16 + (lane >> 2);
        int r1 = r0 + 8;
        #pragma unroll
        for (int nt = 0; nt < 4; nt++) {
            int cl = wn + nt * 8 + (lane & 3) * 2;
            float b0 = sbias[cl], b1 = sbias[cl + 1];
            float v0 = acc[mt][nt][0] + b0;
            float v1 = acc[mt][nt][1] + b1;
            float v2 = acc[mt][nt][2] + b0;
            float v3 = acc[mt][nt][3] + b1;
            if (mode == 0) {
                v0 = fmaxf(v0, 0.f); v1 = fmaxf(v1, 0.f);
                v2 = fmaxf(v2, 0.f); v3 = fmaxf(v3, 0.f);
                if (r0 < NN)
                    *(__half2*)(C16 + (size_t)r0 * 256 + n0 + cl) = __floats2half2_rn(v0, v1);
                if (r1 < NN)
                    *(__half2*)(C16 + (size_t)r1 * 256 + n0 + cl) = __floats2half2_rn(v2, v3);
            } else {
                if (r0 < NN)
                    *(float2*)(C32 + (size_t)r0 * 256 + n0 + cl) = make_float2(v0, v1);
                if (r1 < NN)
                    *(float2*)(C32 + (size_t)r1 * 256 + n0 + cl) = make_float2(v2, v3);
            }
        }
    }
}

// ---------------- heads ----------------
__global__ void heads_kernel(const float* __restrict__ H, const float* __restrict__ Wp,
                             const float* __restrict__ bp, const float* __restrict__ Wv,
                             float* __restrict__ out) {
    int gw   = (blockIdx.x * blockDim.x + threadIdx.x) >> 5;
    int lane = threadIdx.x & 31;
    int nwrp = (gridDim.x * blockDim.x) >> 5;
    const float4* p4 = (const float4*)Wp;
    const float4* v4 = (const float4*)Wv;
    for (int n = gw; n < NN; n += nwrp) {
        const float4* h4 = (const float4*)(H + (size_t)n * 256);
        float4 h0 = h4[lane], h1 = h4[lane + 32];
        float4 a0 = p4[lane], a1 = p4[lane + 32];
        float4 b0 = v4[lane], b1 = v4[lane + 32];
        float dp = h0.x * a0.x + h0.y * a0.y + h0.z * a0.z + h0.w * a0.w
                 + h1.x * a1.x + h1.y * a1.y + h1.z * a1.z + h1.w * a1.w;
        float dv = h0.x * b0.x + h0.y * b0.y + h0.z * b0.z + h0.w * b0.w
                 + h1.x * b1.x + h1.y * b1.y + h1.z * b1.z + h1.w * b1.w;
        #pragma unroll
        for (int o = 16; o > 0; o >>= 1) {
            dp += __shfl_xor_sync(0xffffffffu, dp, o);
            dv += __shfl_xor_sync(0xffffffffu, dv, o);
        }
        if (lane == 0) {
            out[n] = dp + bp[0];
            atomicAdd(&g_vsum, dv);
        }
    }
}

__global__ void final_kernel(const float* __restrict__ bv, float* __restrict__ out) {
    if (threadIdx.x == 0)
        out[NN] = g_vsum * (1.0f / (float)NN) + bv[0];
}

// ---------------- launch ----------------
extern "C" void kernel_launch(void* const* d_in, const int* in_sizes, int n_in,
                              void* d_out, int out_size) {
    const float* features = (const float*)d_in[0];
    const int*   src      = (const int*)d_in[1];
    const int*   dst      = (const int*)d_in[2];
    const float* W1 = (const float*)d_in[3];
    const float* b1 = (const float*)d_in[4];
    const float* W2 = (const float*)d_in[5];
    const float* b2 = (const float*)d_in[6];
    const float* W3 = (const float*)d_in[7];
    const float* b3 = (const float*)d_in[8];
    const float* Wp = (const float*)d_in[9];
    const float* bp = (const float*)d_in[10];
    const float* Wv = (const float*)d_in[11];
    const float* bv = (const float*)d_in[12];
    float* out = (float*)d_out;

    void *pBuf_, *pX16_, *pAhi_, *pAlo_, *pWhi_, *pWlo_;
    cudaGetSymbolAddress(&pBuf_, g_buf);
    cudaGetSymbolAddress(&pX16_, g_x16);
    cudaGetSymbolAddress(&pAhi_, g_ahi);
    cudaGetSymbolAddress(&pAlo_, g_alo);
    cudaGetSymbolAddress(&pWhi_, g_whi);
    cudaGetSymbolAddress(&pWlo_, g_wlo);
    float* buf = (float*)pBuf_;
    __half* x16 = (__half*)pX16_;
    __nv_bfloat16* ahi = (__nv_bfloat16*)pAhi_;
    __nv_bfloat16* alo = (__nv_bfloat16*)pAlo_;
    __nv_bfloat16* whi = (__nv_bfloat16*)pWhi_;
    __nv_bfloat16* wlo = (__nv_bfloat16*)pWlo_;

    // graph preprocessing
    zero_kernel<<<(NN + 255) / 256, 256>>>();
    count_kernel<<<(NE + 255) / 256, 256>>>(src, dst);
    scan_kernel<<<1, 1024>>>();
    fill_kernel<<<(NE + 255) / 256, 256>>>(src, dst);

    // conversions
    convert_x16<<<(NN * 128 / 2 + 255) / 256, 256>>>(features, NN * 128);
    convert_w<<<64, 256>>>(W1, 128 * 256, 0);
    convert_w<<<128, 256>>>(W2, 256 * 256, 32768);
    convert_w<<<128, 256>>>(W3, 256 * 256, 98304);

    dim3 ggrid(79, 2);

    // layer 1 (K=128): agg fp16 -> GEMM (relu, fp16 out to x16)
    aggregate_kernel<1><<<1250, 256>>>(x16, ahi, alo, 128);
    gemm_mma<<<ggrid, 256>>>(ahi, alo, whi, wlo, b1, buf, x16, 128, 0);
    // layer 2 (K=256)
    aggregate_kernel<2><<<1250, 256>>>(x16, ahi, alo, 256);
    gemm_mma<<<ggrid, 256>>>(ahi, alo, whi + 32768, wlo + 32768, b2, buf, x16, 256, 0);
    // layer 3 (K=256): fp32 out, no act
    aggregate_kernel<2><<<1250, 256>>>(x16, ahi, alo, 256);
    gemm_mma<<<ggrid, 256>>>(ahi, alo, whi + 98304, wlo + 98304, b3, buf, x16, 256, 1);

    // heads
    heads_kernel<<<1250, 256>>>(buf, Wp, bp, Wv, out);
    final_kernel<<<1, 32>>>(bv, out);
}

// round 7
// speedup vs baseline: 1.3575x; 1.3575x over previous
#include <cuda_runtime.h>
#include <cuda_bf16.h>
#include <cuda_fp16.h>
#include <cstdint>

#define NN 10000
#define NE 320000
#define F_HID 256

// ---------------- scratch (device globals; no allocation allowed) ----------------
__device__ int   g_deg[NN];
__device__ int   g_incnt[NN];
__device__ int   g_roff[NN];                        // CSR bucket start (order-free alloc)
__device__ int   g_rend[NN];                        // CSR bucket end
__device__ int   g_rank[NE];
__device__ int   g_total;
__device__ float g_inv[NN];
__device__ int2  g_csr[NE];                         // (src, w bits)
__device__ float g_buf[NN * F_HID];                 // fp32 layer-3 output
__device__ __align__(16) __half g_x16[NN * F_HID];  // fp16 gather operand
__device__ __nv_bfloat16 g_ahi[NN * F_HID];
__device__ __nv_bfloat16 g_alo[NN * F_HID];
__device__ __nv_bfloat16 g_whi[256 * 256 * 3];
__device__ __nv_bfloat16 g_wlo[256 * 256 * 3];
__device__ float g_vsum;

// ---------------- helpers ----------------
__device__ __forceinline__ void cvt_hilo2(float x0, float x1, uint32_t& hip, uint32_t& lop) {
    __nv_bfloat162 h = __floats2bfloat162_rn(x0, x1);
    float h0 = __bfloat162float(__low2bfloat16(h));
    float h1 = __bfloat162float(__high2bfloat16(h));
    __nv_bfloat162 l = __floats2bfloat162_rn(x0 - h0, x1 - h1);
    hip = *reinterpret_cast<uint32_t*>(&h);
    lop = *reinterpret_cast<uint32_t*>(&l);
}

__device__ __forceinline__ void ldsm4(uint32_t* r, uint32_t addr) {
    asm volatile("ldmatrix.sync.aligned.m8n8.x4.shared.b16 {%0,%1,%2,%3}, [%4];"
                 : "=r"(r[0]), "=r"(r[1]), "=r"(r[2]), "=r"(r[3]) : "r"(addr));
}
__device__ __forceinline__ void ldsm4t(uint32_t* r, uint32_t addr) {
    asm volatile("ldmatrix.sync.aligned.m8n8.x4.trans.shared.b16 {%0,%1,%2,%3}, [%4];"
                 : "=r"(r[0]), "=r"(r[1]), "=r"(r[2]), "=r"(r[3]) : "r"(addr));
}
__device__ __forceinline__ void mma16816(float* c, const uint32_t* a, const uint32_t* b) {
    asm volatile(
        "mma.sync.aligned.m16n8k16.row.col.f32.bf16.bf16.f32 "
        "{%0,%1,%2,%3}, {%4,%5,%6,%7}, {%8,%9}, {%0,%1,%2,%3};"
        : "+f"(c[0]), "+f"(c[1]), "+f"(c[2]), "+f"(c[3])
        : "r"(a[0]), "r"(a[1]), "r"(a[2]), "r"(a[3]), "r"(b[0]), "r"(b[1]));
}

// ---------------- graph preprocessing ----------------
__global__ void zero_kernel() {
    int i = blockIdx.x * blockDim.x + threadIdx.x;
    if (i < NN) { g_deg[i] = 0; g_incnt[i] = 0; }
    if (i == 0) { g_vsum = 0.0f; g_total = 0; }
}

__global__ void count_kernel(const int* __restrict__ src, const int* __restrict__ dst) {
    int e = blockIdx.x * blockDim.x + threadIdx.x;
    if (e < NE) {
        atomicAdd(&g_deg[src[e]], 1);
        g_rank[e] = atomicAdd(&g_incnt[dst[e]], 1);
    }
}

// order-free CSR bucket allocation (replaces the serial prefix scan)
__global__ void alloc_kernel() {
    int i = blockIdx.x * blockDim.x + threadIdx.x;
    if (i < NN) {
        int c = g_incnt[i];
        int base = atomicAdd(&g_total, c);
        g_roff[i] = base;
        g_rend[i] = base + c;
        int d = g_deg[i];
        g_inv[i] = (d > 0) ? 1.0f / (float)d : 0.0f;
    }
}

__global__ void fill_kernel(const int* __restrict__ src, const int* __restrict__ dst) {
    int e = blockIdx.x * blockDim.x + threadIdx.x;
    if (e < NE) {
        int d = dst[e];
        int s = src[e];
        int p = g_roff[d] + g_rank[e];
        g_csr[p] = make_int2(s, __float_as_int(g_inv[s]));
    }
}

// ---------------- fused conversions: features->fp16, W1/W2/W3 -> bf16 hi/lo ----------------
#define NFP (NN * 128 / 2)          // 640000 feature pairs
#define W1P (128 * 256 / 2)         // 16384
#define W2P (256 * 256 / 2)         // 32768
__global__ void convert_all(const float* __restrict__ X, const float* __restrict__ W1,
                            const float* __restrict__ W2, const float* __restrict__ W3) {
    int t = blockIdx.x * blockDim.x + threadIdx.x;
    if (t < NFP) {
        float2 v = *(const float2*)(X + 2 * t);
        __half2 h = __floats2half2_rn(v.x, v.y);
        *(uint32_t*)((char*)g_x16 + 4 * t) = *reinterpret_cast<uint32_t*>(&h);
        return;
    }
    int u = t - NFP;
    const float* Wsrc;
    int off;
    if (u < W1P) { Wsrc = W1; off = 0; }
    else if (u < W1P + W2P) { Wsrc = W2; off = 32768; u -= W1P; }
    else if (u < W1P + 2 * W2P) { Wsrc = W3; off = 98304; u -= W1P + W2P; }
    else return;
    float2 v = *(const float2*)(Wsrc + 2 * u);
    uint32_t hip, lop;
    cvt_hilo2(v.x, v.y, hip, lop);
    *(uint32_t*)((char*)g_whi + 2 * (off + 2 * u)) = hip;
    *(uint32_t*)((char*)g_wlo + 2 * (off + 2 * u)) = lop;
}

// ---------------- edge aggregation (fp16 gather, fp32 accum, MLP=4) -> bf16 hi/lo ----------------
template <int CHUNKS>  // 1: F=128, 2: F=256
__global__ void aggregate_kernel(const __half* __restrict__ X,
                                 __nv_bfloat16* __restrict__ Yhi,
                                 __nv_bfloat16* __restrict__ Ylo, int F) {
    int gw    = (blockIdx.x * blockDim.x + threadIdx.x) >> 5;
    int lane  = threadIdx.x & 31;
    int nwrp  = (gridDim.x * blockDim.x) >> 5;
    for (int n = gw; n < NN; n += nwrp) {
        int s0 = g_roff[n], s1 = g_rend[n];
        float4 acc0 = make_float4(0.f, 0.f, 0.f, 0.f);
        float4 acc1 = make_float4(0.f, 0.f, 0.f, 0.f);
        for (int e0 = s0; e0 < s1; e0 += 32) {
            int   ss = 0; float ww = 0.f;
            if (e0 + lane < s1) {
                int2 ev = g_csr[e0 + lane];
                ss = ev.x; ww = __int_as_float(ev.y);
            }
            int cnt = min(32, s1 - e0);
            int j = 0;
            // 4-way unrolled: 4 independent gathers in flight
            for (; j + 4 <= cnt; j += 4) {
                int sj0 = __shfl_sync(0xffffffffu, ss, j);
                int sj1 = __shfl_sync(0xffffffffu, ss, j + 1);
                int sj2 = __shfl_sync(0xffffffffu, ss, j + 2);
                int sj3 = __shfl_sync(0xffffffffu, ss, j + 3);
                float w0 = __shfl_sync(0xffffffffu, ww, j);
                float w1 = __shfl_sync(0xffffffffu, ww, j + 1);
                float w2 = __shfl_sync(0xffffffffu, ww, j + 2);
                float w3 = __shfl_sync(0xffffffffu, ww, j + 3);
                if (CHUNKS == 1) {
                    uint2 v0 = ((const uint2*)(X + (size_t)sj0 * F))[lane];
                    uint2 v1 = ((const uint2*)(X + (size_t)sj1 * F))[lane];
                    uint2 v2 = ((const uint2*)(X + (size_t)sj2 * F))[lane];
                    uint2 v3 = ((const uint2*)(X + (size_t)sj3 * F))[lane];
                    #define ACC2(vv, wj) { \
                        float2 f0 = __half22float2(*reinterpret_cast<__half2*>(&(vv).x)); \
                        float2 f1 = __half22float2(*reinterpret_cast<__half2*>(&(vv).y)); \
                        acc0.x += (wj) * f0.x; acc0.y += (wj) * f0.y; \
                        acc0.z += (wj) * f1.x; acc0.w += (wj) * f1.y; }
                    ACC2(v0, w0) ACC2(v1, w1) ACC2(v2, w2) ACC2(v3, w3)
                    #undef ACC2
                } else {
                    uint4 v0 = ((const uint4*)(X + (size_t)sj0 * F))[lane];
                    uint4 v1 = ((const uint4*)(X + (size_t)sj1 * F))[lane];
                    uint4 v2 = ((const uint4*)(X + (size_t)sj2 * F))[lane];
                    uint4 v3 = ((const uint4*)(X + (size_t)sj3 * F))[lane];
                    #define ACC4(vv, wj) { \
                        float2 f0 = __half22float2(*reinterpret_cast<__half2*>(&(vv).x)); \
                        float2 f1 = __half22float2(*reinterpret_cast<__half2*>(&(vv).y)); \
                        float2 f2 = __half22float2(*reinterpret_cast<__half2*>(&(vv).z)); \
                        float2 f3 = __half22float2(*reinterpret_cast<__half2*>(&(vv).w)); \
                        acc0.x += (wj) * f0.x; acc0.y += (wj) * f0.y; \
                        acc0.z += (wj) * f1.x; acc0.w += (wj) * f1.y; \
                        acc1.x += (wj) * f2.x; acc1.y += (wj) * f2.y; \
                        acc1.z += (wj) * f3.x; acc1.w += (wj) * f3.y; }
                    ACC4(v0, w0) ACC4(v1, w1) ACC4(v2, w2) ACC4(v3, w3)
                    #undef ACC4
                }
            }
            for (; j < cnt; j++) {
                int   sj = __shfl_sync(0xffffffffu, ss, j);
                float wj = __shfl_sync(0xffffffffu, ww, j);
                if (CHUNKS == 1) {
                    uint2 v = ((const uint2*)(X + (size_t)sj * F))[lane];
                    float2 f0 = __half22float2(*reinterpret_cast<__half2*>(&v.x));
                    float2 f1 = __half22float2(*reinterpret_cast<__half2*>(&v.y));
                    acc0.x += wj * f0.x; acc0.y += wj * f0.y;
                    acc0.z += wj * f1.x; acc0.w += wj * f1.y;
                } else {
                    uint4 v = ((const uint4*)(X + (size_t)sj * F))[lane];
                    float2 f0 = __half22float2(*reinterpret_cast<__half2*>(&v.x));
                    float2 f1 = __half22float2(*reinterpret_cast<__half2*>(&v.y));
                    float2 f2 = __half22float2(*reinterpret_cast<__half2*>(&v.z));
                    float2 f3 = __half22float2(*reinterpret_cast<__half2*>(&v.w));
                    acc0.x += wj * f0.x; acc0.y += wj * f0.y;
                    acc0.z += wj * f1.x; acc0.w += wj * f1.y;
                    acc1.x += wj * f2.x; acc1.y += wj * f2.y;
                    acc1.z += wj * f3.x; acc1.w += wj * f3.y;
                }
            }
        }
        uint32_t h01, l01, h23, l23;
        cvt_hilo2(acc0.x, acc0.y, h01, l01);
        cvt_hilo2(acc0.z, acc0.w, h23, l23);
        if (CHUNKS == 1) {
            ((uint2*)(Yhi + (size_t)n * F))[lane] = make_uint2(h01, h23);
            ((uint2*)(Ylo + (size_t)n * F))[lane] = make_uint2(l01, l23);
        } else {
            uint32_t h45, l45, h67, l67;
            cvt_hilo2(acc1.x, acc1.y, h45, l45);
            cvt_hilo2(acc1.z, acc1.w, h67, l67);
            ((uint4*)(Yhi + (size_t)n * F))[lane] = make_uint4(h01, h23, h45, h67);
            ((uint4*)(Ylo + (size_t)n * F))[lane] = make_uint4(l01, l23, l45, l67);
        }
    }
}

// ---------------- GEMM via mma.sync bf16 hi/lo ----------------
// CTA tile 160x128, 8 warps (2m x 4n), warp tile 80x32, BK=32 -> 126 CTAs (single wave)
#define MT 160
#define AS_STRIDE 40
#define BS_STRIDE 136
__global__ void __launch_bounds__(256)
gemm_mma(const __nv_bfloat16* __restrict__ Ahi, const __nv_bfloat16* __restrict__ Alo,
         const __nv_bfloat16* __restrict__ Whi, const __nv_bfloat16* __restrict__ Wlo,
         const float* __restrict__ bias, float* __restrict__ C32,
         __half* __restrict__ C16, int K, int mode) {
    __shared__ __align__(16) __nv_bfloat16 sAhi[MT * AS_STRIDE];
    __shared__ __align__(16) __nv_bfloat16 sAlo[MT * AS_STRIDE];
    __shared__ __align__(16) __nv_bfloat16 sBhi[32 * BS_STRIDE];
    __shared__ __align__(16) __nv_bfloat16 sBlo[32 * BS_STRIDE];
    __shared__ float sbias[128];

    int tid = threadIdx.x;
    int m0 = blockIdx.x * MT, n0 = blockIdx.y * 128;
    if (tid < 128) sbias[tid] = bias[n0 + tid];
    int wid = tid >> 5, lane = tid & 31;
    int wm = (wid & 1) * 80, wn = (wid >> 1) * 32;

    float acc[5][4][4];
    #pragma unroll
    for (int i = 0; i < 5; i++)
        #pragma unroll
        for (int j = 0; j < 4; j++)
            #pragma unroll
            for (int q = 0; q < 4; q++) acc[i][j][q] = 0.f;

    const uint4 z4 = make_uint4(0, 0, 0, 0);

    for (int kc = 0; kc < K; kc += 32) {
        // stage A: MT rows x 32 k (MT*4 = 640 uint4 per array)
        #pragma unroll
        for (int idx = tid; idx < MT * 4; idx += 256) {
            int row = idx >> 2, c16 = idx & 3;
            int gr = m0 + row;
            uint4 vh = z4, vl = z4;
            if (gr < NN) {
                vh = *(const uint4*)(Ahi + (size_t)gr * K + kc + c16 * 8);
                vl = *(const uint4*)(Alo + (size_t)gr * K + kc + c16 * 8);
            }
            *(uint4*)(sAhi + row * AS_STRIDE + c16 * 8) = vh;
            *(uint4*)(sAlo + row * AS_STRIDE + c16 * 8) = vl;
        }
        // stage B: 32 k rows x 128 n
        #pragma unroll
        for (int idx = tid; idx < 512; idx += 256) {
            int row = idx >> 4, c16 = idx & 15;
            *(uint4*)(sBhi + row * BS_STRIDE + c16 * 8) =
                *(const uint4*)(Whi + (size_t)(kc + row) * 256 + n0 + c16 * 8);
            *(uint4*)(sBlo + row * BS_STRIDE + c16 * 8) =
                *(const uint4*)(Wlo + (size_t)(kc + row) * 256 + n0 + c16 * 8);
        }
        __syncthreads();

        #pragma unroll
        for (int k16 = 0; k16 < 2; k16++) {
            uint32_t ah[5][4], al[5][4], bh[4][2], bl[4][2];
            #pragma unroll
            for (int mt = 0; mt < 5; mt++) {
                int row = wm + mt * 16 + (lane & 15);
                int col = k16 * 16 + (lane >> 4) * 8;
                uint32_t ad = (uint32_t)__cvta_generic_to_shared(sAhi + row * AS_STRIDE + col);
                ldsm4(ah[mt], ad);
                ad = (uint32_t)__cvta_generic_to_shared(sAlo + row * AS_STRIDE + col);
                ldsm4(al[mt], ad);
            }
            #pragma unroll
            for (int nt2 = 0; nt2 < 2; nt2++) {
                int row = k16 * 16 + (lane & 15);
                int col = wn + nt2 * 16 + ((lane >> 4) & 1) * 8;
                uint32_t t[4];
                uint32_t ad = (uint32_t)__cvta_generic_to_shared(sBhi + row * BS_STRIDE + col);
                ldsm4t(t, ad);
                bh[nt2 * 2][0] = t[0]; bh[nt2 * 2][1] = t[1];
                bh[nt2 * 2 + 1][0] = t[2]; bh[nt2 * 2 + 1][1] = t[3];
                ad = (uint32_t)__cvta_generic_to_shared(sBlo + row * BS_STRIDE + col);
                ldsm4t(t, ad);
                bl[nt2 * 2][0] = t[0]; bl[nt2 * 2][1] = t[1];
                bl[nt2 * 2 + 1][0] = t[2]; bl[nt2 * 2 + 1][1] = t[3];
            }
            #pragma unroll
            for (int mt = 0; mt < 5; mt++)
                #pragma unroll
                for (int nt = 0; nt < 4; nt++) {
                    mma16816(acc[mt][nt], ah[mt], bh[nt]);
                    mma16816(acc[mt][nt], ah[mt], bl[nt]);
                    mma16816(acc[mt][nt], al[mt], bh[nt]);
                }
        }
        __syncthreads();
    }

    // epilogue
    #pragma unroll
    for (int mt = 0; mt < 5; mt++) {
        int r0 = m0 + wm + mt * 16 + (lane >> 2);
        int r1 = r0 + 8;
        #pragma unroll
        for (int nt = 0; nt < 4; nt++) {
            int cl = wn + nt * 8 + (lane & 3) * 2;
            float b0 = sbias[cl], b1 = sbias[cl + 1];
            float v0 = acc[mt][nt][0] + b0;
            float v1 = acc[mt][nt][1] + b1;
            float v2 = acc[mt][nt][2] + b0;
            float v3 = acc[mt][nt][3] + b1;
            if (mode == 0) {
                v0 = fmaxf(v0, 0.f); v1 = fmaxf(v1, 0.f);
                v2 = fmaxf(v2, 0.f); v3 = fmaxf(v3, 0.f);
                if (r0 < NN)
                    *(__half2*)(C16 + (size_t)r0 * 256 + n0 + cl) = __floats2half2_rn(v0, v1);
                if (r1 < NN)
                    *(__half2*)(C16 + (size_t)r1 * 256 + n0 + cl) = __floats2half2_rn(v2, v3);
            } else {
                if (r0 < NN)
                    *(float2*)(C32 + (size_t)r0 * 256 + n0 + cl) = make_float2(v0, v1);
                if (r1 < NN)
                    *(float2*)(C32 + (size_t)r1 * 256 + n0 + cl) = make_float2(v2, v3);
            }
        }
    }
}

// ---------------- heads (block-reduced vsum atomic) ----------------
__global__ void heads_kernel(const float* __restrict__ H, const float* __restrict__ Wp,
                             const float* __restrict__ bp, const float* __restrict__ Wv,
                             float* __restrict__ out) {
    __shared__ float sred[8];
    int gw   = (blockIdx.x * blockDim.x + threadIdx.x) >> 5;
    int wloc = threadIdx.x >> 5;
    int lane = threadIdx.x & 31;
    int nwrp = (gridDim.x * blockDim.x) >> 5;
    const float4* p4 = (const float4*)Wp;
    const float4* v4 = (const float4*)Wv;
    float vloc = 0.f;
    for (int n = gw; n < NN; n += nwrp) {
        const float4* h4 = (const float4*)(H + (size_t)n * 256);
        float4 h0 = h4[lane], h1 = h4[lane + 32];
        float4 a0 = p4[lane], a1 = p4[lane + 32];
        float4 b0 = v4[lane], b1 = v4[lane + 32];
        float dp = h0.x * a0.x + h0.y * a0.y + h0.z * a0.z + h0.w * a0.w
                 + h1.x * a1.x + h1.y * a1.y + h1.z * a1.z + h1.w * a1.w;
        float dv = h0.x * b0.x + h0.y * b0.y + h0.z * b0.z + h0.w * b0.w
                 + h1.x * b1.x + h1.y * b1.y + h1.z * b1.z + h1.w * b1.w;
        #pragma unroll
        for (int o = 16; o > 0; o >>= 1) {
            dp += __shfl_xor_sync(0xffffffffu, dp, o);
            dv += __shfl_xor_sync(0xffffffffu, dv, o);
        }
        if (lane == 0) out[n] = dp + bp[0];
        vloc += dv;  // same value in all lanes post-reduce
    }
    if (lane == 0) sred[wloc] = vloc;
    __syncthreads();
    if (threadIdx.x == 0) {
        float s = 0.f;
        #pragma unroll
        for (int w = 0; w < 8; w++) s += sred[w];
        atomicAdd(&g_vsum, s);
    }
}

__global__ void final_kernel(const float* __restrict__ bv, float* __restrict__ out) {
    if (threadIdx.x == 0)
        out[NN] = g_vsum * (1.0f / (float)NN) + bv[0];
}

// ---------------- launch ----------------
extern "C" void kernel_launch(void* const* d_in, const int* in_sizes, int n_in,
                              void* d_out, int out_size) {
    const float* features = (const float*)d_in[0];
    const int*   src      = (const int*)d_in[1];
    const int*   dst      = (const int*)d_in[2];
    const float* W1 = (const float*)d_in[3];
    const float* b1 = (const float*)d_in[4];
    const float* W2 = (const float*)d_in[5];
    const float* b2 = (const float*)d_in[6];
    const float* W3 = (const float*)d_in[7];
    const float* b3 = (const float*)d_in[8];
    const float* Wp = (const float*)d_in[9];
    const float* bp = (const float*)d_in[10];
    const float* Wv = (const float*)d_in[11];
    const float* bv = (const float*)d_in[12];
    float* out = (float*)d_out;

    void *pBuf_, *pX16_, *pAhi_, *pAlo_, *pWhi_, *pWlo_;
    cudaGetSymbolAddress(&pBuf_, g_buf);
    cudaGetSymbolAddress(&pX16_, g_x16);
    cudaGetSymbolAddress(&pAhi_, g_ahi);
    cudaGetSymbolAddress(&pAlo_, g_alo);
    cudaGetSymbolAddress(&pWhi_, g_whi);
    cudaGetSymbolAddress(&pWlo_, g_wlo);
    float* buf = (float*)pBuf_;
    __half* x16 = (__half*)pX16_;
    __nv_bfloat16* ahi = (__nv_bfloat16*)pAhi_;
    __nv_bfloat16* alo = (__nv_bfloat16*)pAlo_;
    __nv_bfloat16* whi = (__nv_bfloat16*)pWhi_;
    __nv_bfloat16* wlo = (__nv_bfloat16*)pWlo_;

    // graph preprocessing (order-free CSR)
    zero_kernel<<<(NN + 255) / 256, 256>>>();
    count_kernel<<<(NE + 255) / 256, 256>>>(src, dst);
    alloc_kernel<<<(NN + 255) / 256, 256>>>();
    fill_kernel<<<(NE + 255) / 256, 256>>>(src, dst);

    // fused conversions (features + all weights)
    int conv_threads = NFP + W1P + 2 * W2P;
    convert_all<<<(conv_threads + 255) / 256, 256>>>(features, W1, W2, W3);

    dim3 ggrid((NN + MT - 1) / MT, 2);  // 63 x 2 = 126 CTAs

    // layer 1 (K=128)
    aggregate_kernel<1><<<1250, 256>>>(x16, ahi, alo, 128);
    gemm_mma<<<ggrid, 256>>>(ahi, alo, whi, wlo, b1, buf, x16, 128, 0);
    // layer 2 (K=256)
    aggregate_kernel<2><<<1250, 256>>>(x16, ahi, alo, 256);
    gemm_mma<<<ggrid, 256>>>(ahi, alo, whi + 32768, wlo + 32768, b2, buf, x16, 256, 0);
    // layer 3 (K=256): fp32 out, no act
    aggregate_kernel<2><<<1250, 256>>>(x16, ahi, alo, 256);
    gemm_mma<<<ggrid, 256>>>(ahi, alo, whi + 98304, wlo + 98304, b3, buf, x16, 256, 1);

    // heads
    heads_kernel<<<1250, 256>>>(buf, Wp, bp, Wv, out);
    final_kernel<<<1, 32>>>(bv, out);
}